// round 3
// baseline (speedup 1.0000x reference)
#include <cuda_runtime.h>
#include <cstdint>

#define MAXG 1024
#define RESI 256
#define GSPLIT 8
#define GCHUNK 128   // MAXG / GSPLIT
#define NBLK 128     // pixel blocks (16x32 px each)

__device__ float    d_partial[GSPLIT * RESI * RESI];   // 2 MB scratch
__device__ unsigned d_count[NBLK];                     // zero-init; +8 per call per blk

__device__ __forceinline__ float ex2f(float x) {
    float y;
    asm("ex2.approx.ftz.f32 %0, %1;" : "=f"(y) : "f"(x));
    return y;
}

// ---------------------------------------------------------------------------
// Single fused kernel:
//   grid = NBLK * GSPLIT CTAs, 128 threads.
//   Phase 1: per-CTA prep of its 128-gaussian chunk into smem (1 gauss/thread)
//   Phase 2: splat 16(w) x 32(h) pixel block over the chunk (4 px/thread),
//            warp entirely inside one 16x16 tile -> warp-uniform mask skip
//   Phase 3: write partial; last CTA per pixel block sums 8 partials in fixed
//            order (deterministic) and writes the output.
// ---------------------------------------------------------------------------
__global__ void __launch_bounds__(128) splat_fused(
        const float* __restrict__ xyz,
        const float* __restrict__ scaling,
        const float* __restrict__ rotation,
        const float* __restrict__ opacity,
        const float* __restrict__ rot,
        float* __restrict__ out,
        int N) {
    __shared__ float4 s0[GCHUNK];
    __shared__ float4 s1[GCHUNK];

    const float RES = (float)RESI;
    int bid = blockIdx.x;
    int s   = bid & (GSPLIT - 1);   // gaussian split
    int blk = bid >> 3;             // pixel block 0..127

    int g0 = s * GCHUNK;
    int gN = N - g0;
    if (gN > GCHUNK) gN = GCHUNK;
    if (gN < 0) gN = 0;

    int t = threadIdx.x;

    // ---- Phase 1: prep (one gaussian per thread) ----
    if (t < gN) {
        int i = g0 + t;
        float qr = rotation[4 * i + 0];
        float qx = rotation[4 * i + 1];
        float qy = rotation[4 * i + 2];
        float qz = rotation[4 * i + 3];
        float inv = rsqrtf(qr * qr + qx * qx + qy * qy + qz * qz);
        qr *= inv; qx *= inv; qy *= inv; qz *= inv;

        float R00 = 1.f - 2.f * (qy * qy + qz * qz);
        float R01 = 2.f * (qx * qy - qr * qz);
        float R02 = 2.f * (qx * qz + qr * qy);
        float R10 = 2.f * (qx * qy + qr * qz);
        float R11 = 1.f - 2.f * (qx * qx + qz * qz);
        float R12 = 2.f * (qy * qz - qr * qx);
        float R20 = 2.f * (qx * qz - qr * qy);
        float R21 = 2.f * (qy * qz + qr * qx);
        float R22 = 1.f - 2.f * (qx * qx + qy * qy);

        float sc0 = scaling[3 * i + 0];
        float sc1 = scaling[3 * i + 1];
        float sc2 = scaling[3 * i + 2];

        float L00 = R00 * sc0, L01 = R01 * sc1, L02 = R02 * sc2;
        float L10 = R10 * sc0, L11 = R11 * sc1, L12 = R12 * sc2;
        float L20 = R20 * sc0, L21 = R21 * sc1, L22 = R22 * sc2;

        float C00 = L00 * L00 + L01 * L01 + L02 * L02;
        float C01 = L00 * L10 + L01 * L11 + L02 * L12;
        float C02 = L00 * L20 + L01 * L21 + L02 * L22;
        float C11 = L10 * L10 + L11 * L11 + L12 * L12;
        float C12 = L10 * L20 + L11 * L21 + L12 * L22;
        float C22 = L20 * L20 + L21 * L21 + L22 * L22;

        float a00 = RES * rot[0], a01 = RES * rot[1], a02 = RES * rot[2];
        float a10 = RES * rot[3], a11 = RES * rot[4], a12 = RES * rot[5];

        float v0x = C00 * a00 + C01 * a01 + C02 * a02;
        float v0y = C01 * a00 + C11 * a01 + C12 * a02;
        float v0z = C02 * a00 + C12 * a01 + C22 * a02;
        float c00 = a00 * v0x + a01 * v0y + a02 * v0z;
        float c01 = a10 * v0x + a11 * v0y + a12 * v0z;
        float v1x = C00 * a10 + C01 * a11 + C02 * a12;
        float v1y = C01 * a10 + C11 * a11 + C12 * a12;
        float v1z = C02 * a10 + C12 * a11 + C22 * a12;
        float c11 = a10 * v1x + a11 * v1y + a12 * v1z;

        float det = c00 * c11 - c01 * c01;
        float mid = 0.5f * (c00 + c11);
        float sq = sqrtf(fmaxf(mid * mid - det, 0.1f));
        float lam = fmaxf(mid + sq, mid - sq);
        float radii = ceilf(3.0f * sqrtf(lam));

        float mx = xyz[3 * i + 0] * (RES * 0.5f);
        float my = xyz[3 * i + 1] * (RES * 0.5f);

        float rminx = fminf(fmaxf(mx - radii, 0.f), RES - 1.f);
        float rmaxx = fminf(fmaxf(mx + radii, 0.f), RES - 1.f);
        float rminy = fminf(fmaxf(my - radii, 0.f), RES - 1.f);
        float rmaxy = fminf(fmaxf(my + radii, 0.f), RES - 1.f);

        unsigned mw = 0u;
        #pragma unroll
        for (int tt = 0; tt < 16; tt++) {
            float ts = (float)(tt * 16);
            if (fminf(rmaxx, ts + 15.f) > fmaxf(rminx, ts)) mw |= (1u << tt);
            if (fminf(rmaxy, ts + 15.f) > fmaxf(rminy, ts)) mw |= (1u << (16 + tt));
        }

        float idet = 1.0f / det;
        const float L2E = 1.4426950408889634f;
        float cA = -0.5f * L2E * (c11 * idet);
        float cB = -0.5f * L2E * (c00 * idet);
        float cC = -0.5f * L2E * (-2.0f * c01 * idet);

        s0[t] = make_float4(mx, my, cA, cB);
        s1[t] = make_float4(cC, opacity[i], __uint_as_float(mw), 0.f);
    }
    __syncthreads();

    // ---- Phase 2: splat ----
    int bx = blk & 15;              // tile column 0..15
    int by = blk >> 4;              // block row 0..7 (each 32px tall)
    int cg  = t & 3;
    int row = t >> 2;               // 0..31
    int x = bx * 16 + cg * 4;
    int y = by * 32 + row;
    unsigned need = (1u << bx) | (1u << (16 + (y >> 4)));

    float px = (float)x - 127.5f;
    float py = (float)y - 127.5f;

    float a0 = 0.f, a1 = 0.f, a2 = 0.f, a3 = 0.f;

    #pragma unroll 2
    for (int i = 0; i < gN; i++) {
        float4 q1 = s1[i];
        unsigned mw = __float_as_uint(q1.z);
        if ((mw & need) != need) continue;   // warp-uniform skip
        float4 q0 = s0[i];
        float dx = px - q0.x;
        float dy = py - q0.y;
        float h  = q1.x * dy;                // cC * dy
        float sB = q0.w * (dy * dy);         // cB * dy^2
        float o  = q1.y;

        float q, w;
        q = fmaf(dx, fmaf(q0.z, dx, h), sB);
        w = ex2f(q);
        a0 = fmaf(w, o, a0);

        float dxb = dx + 1.f;
        q = fmaf(dxb, fmaf(q0.z, dxb, h), sB);
        w = ex2f(q);
        a1 = fmaf(w, o, a1);

        float dxc = dx + 2.f;
        q = fmaf(dxc, fmaf(q0.z, dxc, h), sB);
        w = ex2f(q);
        a2 = fmaf(w, o, a2);

        float dxd = dx + 3.f;
        q = fmaf(dxd, fmaf(q0.z, dxd, h), sB);
        w = ex2f(q);
        a3 = fmaf(w, o, a3);
    }

    int pix = y * RESI + x;
    *reinterpret_cast<float4*>(&d_partial[s * (RESI * RESI) + pix]) =
        make_float4(a0, a1, a2, a3);

    // ---- Phase 3: last-CTA-per-block reduction (deterministic order) ----
    __threadfence();                 // publish my partial gpu-wide
    __syncthreads();                 // all threads of this CTA fenced
    __shared__ unsigned s_old;
    if (t == 0) s_old = atomicAdd(&d_count[blk], 1u);
    __syncthreads();

    if (((s_old + 1) & (GSPLIT - 1)) == 0) {
        // I'm the last of the 8 CTAs for this pixel block: reduce in fixed order.
        const float4* p = reinterpret_cast<const float4*>(d_partial);
        int idx = pix >> 2;          // float4 index of my 4 pixels
        float4 a = __ldcg(&p[idx]);
        #pragma unroll
        for (int ss = 1; ss < GSPLIT; ss++) {
            float4 b = __ldcg(&p[ss * (RESI * RESI / 4) + idx]);
            a.x += b.x; a.y += b.y; a.z += b.z; a.w += b.w;
        }
        *reinterpret_cast<float4*>(&out[pix]) = a;
    }
}

// ---------------------------------------------------------------------------
extern "C" void kernel_launch(void* const* d_in, const int* in_sizes, int n_in,
                              void* d_out, int out_size) {
    const float* xyz      = (const float*)d_in[0];
    const float* scaling  = (const float*)d_in[1];
    const float* rotation = (const float*)d_in[2];
    const float* opacity  = (const float*)d_in[3];
    const float* rot      = (const float*)d_in[4];

    int N = in_sizes[0] / 3;
    if (N > MAXG) N = MAXG;

    splat_fused<<<NBLK * GSPLIT, 128>>>(xyz, scaling, rotation, opacity, rot,
                                        (float*)d_out, N);
}

// round 4
// speedup vs baseline: 1.0010x; 1.0010x over previous
#include <cuda_runtime.h>
#include <cstdint>

#define MAXG 1024
#define RESI 256
#define GSPLIT 16
#define GCHUNK 64    // MAXG / GSPLIT
#define NBLK 128     // pixel blocks (16x32 px each)

__device__ float    d_partial[GSPLIT * RESI * RESI];   // 4 MB scratch
__device__ unsigned d_count[NBLK];                     // zero-init; +GSPLIT per call per blk

__device__ __forceinline__ float ex2f(float x) {
    float y;
    asm("ex2.approx.ftz.f32 %0, %1;" : "=f"(y) : "f"(x));
    return y;
}

// ---------------------------------------------------------------------------
// Single fused kernel:
//   grid = NBLK * GSPLIT CTAs, 128 threads.
//   Phase 1: per-CTA prep of its 64-gaussian chunk into smem (1 gauss/thread)
//   Phase 2: splat 16(w) x 32(h) pixel block over the chunk (4 px/thread),
//            warp entirely inside one 16x16 tile -> warp-uniform mask skip
//   Phase 3: write partial; last CTA per pixel block sums GSPLIT partials in
//            fixed order (deterministic) and writes the output.
// ---------------------------------------------------------------------------
__global__ void __launch_bounds__(128) splat_fused(
        const float* __restrict__ xyz,
        const float* __restrict__ scaling,
        const float* __restrict__ rotation,
        const float* __restrict__ opacity,
        const float* __restrict__ rot,
        float* __restrict__ out,
        int N) {
    __shared__ float4 s0[GCHUNK];
    __shared__ float4 s1[GCHUNK];

    const float RES = (float)RESI;
    int bid = blockIdx.x;
    int s   = bid & (GSPLIT - 1);   // gaussian split
    int blk = bid >> 4;             // pixel block 0..127

    int g0 = s * GCHUNK;
    int gN = N - g0;
    if (gN > GCHUNK) gN = GCHUNK;
    if (gN < 0) gN = 0;

    int t = threadIdx.x;

    // ---- Phase 1: prep (one gaussian per thread; threads 64..127 idle) ----
    if (t < gN) {
        int i = g0 + t;
        float qr = rotation[4 * i + 0];
        float qx = rotation[4 * i + 1];
        float qy = rotation[4 * i + 2];
        float qz = rotation[4 * i + 3];
        float inv = rsqrtf(qr * qr + qx * qx + qy * qy + qz * qz);
        qr *= inv; qx *= inv; qy *= inv; qz *= inv;

        float R00 = 1.f - 2.f * (qy * qy + qz * qz);
        float R01 = 2.f * (qx * qy - qr * qz);
        float R02 = 2.f * (qx * qz + qr * qy);
        float R10 = 2.f * (qx * qy + qr * qz);
        float R11 = 1.f - 2.f * (qx * qx + qz * qz);
        float R12 = 2.f * (qy * qz - qr * qx);
        float R20 = 2.f * (qx * qz - qr * qy);
        float R21 = 2.f * (qy * qz + qr * qx);
        float R22 = 1.f - 2.f * (qx * qx + qy * qy);

        float sc0 = scaling[3 * i + 0];
        float sc1 = scaling[3 * i + 1];
        float sc2 = scaling[3 * i + 2];

        float L00 = R00 * sc0, L01 = R01 * sc1, L02 = R02 * sc2;
        float L10 = R10 * sc0, L11 = R11 * sc1, L12 = R12 * sc2;
        float L20 = R20 * sc0, L21 = R21 * sc1, L22 = R22 * sc2;

        float C00 = L00 * L00 + L01 * L01 + L02 * L02;
        float C01 = L00 * L10 + L01 * L11 + L02 * L12;
        float C02 = L00 * L20 + L01 * L21 + L02 * L22;
        float C11 = L10 * L10 + L11 * L11 + L12 * L12;
        float C12 = L10 * L20 + L11 * L21 + L12 * L22;
        float C22 = L20 * L20 + L21 * L21 + L22 * L22;

        float a00 = RES * rot[0], a01 = RES * rot[1], a02 = RES * rot[2];
        float a10 = RES * rot[3], a11 = RES * rot[4], a12 = RES * rot[5];

        float v0x = C00 * a00 + C01 * a01 + C02 * a02;
        float v0y = C01 * a00 + C11 * a01 + C12 * a02;
        float v0z = C02 * a00 + C12 * a01 + C22 * a02;
        float c00 = a00 * v0x + a01 * v0y + a02 * v0z;
        float c01 = a10 * v0x + a11 * v0y + a12 * v0z;
        float v1x = C00 * a10 + C01 * a11 + C02 * a12;
        float v1y = C01 * a10 + C11 * a11 + C12 * a12;
        float v1z = C02 * a10 + C12 * a11 + C22 * a12;
        float c11 = a10 * v1x + a11 * v1y + a12 * v1z;

        float det = c00 * c11 - c01 * c01;
        float mid = 0.5f * (c00 + c11);
        float sq = sqrtf(fmaxf(mid * mid - det, 0.1f));
        float lam = fmaxf(mid + sq, mid - sq);
        float radii = ceilf(3.0f * sqrtf(lam));

        float mx = xyz[3 * i + 0] * (RES * 0.5f);
        float my = xyz[3 * i + 1] * (RES * 0.5f);

        float rminx = fminf(fmaxf(mx - radii, 0.f), RES - 1.f);
        float rmaxx = fminf(fmaxf(mx + radii, 0.f), RES - 1.f);
        float rminy = fminf(fmaxf(my - radii, 0.f), RES - 1.f);
        float rmaxy = fminf(fmaxf(my + radii, 0.f), RES - 1.f);

        unsigned mw = 0u;
        #pragma unroll
        for (int tt = 0; tt < 16; tt++) {
            float ts = (float)(tt * 16);
            if (fminf(rmaxx, ts + 15.f) > fmaxf(rminx, ts)) mw |= (1u << tt);
            if (fminf(rmaxy, ts + 15.f) > fmaxf(rminy, ts)) mw |= (1u << (16 + tt));
        }

        float idet = 1.0f / det;
        const float L2E = 1.4426950408889634f;
        float cA = -0.5f * L2E * (c11 * idet);
        float cB = -0.5f * L2E * (c00 * idet);
        float cC = -0.5f * L2E * (-2.0f * c01 * idet);

        s0[t] = make_float4(mx, my, cA, cB);
        s1[t] = make_float4(cC, opacity[i], __uint_as_float(mw), 0.f);
    }
    __syncthreads();

    // ---- Phase 2: splat ----
    int bx = blk & 15;              // tile column 0..15
    int by = blk >> 4;              // block row 0..7 (each 32px tall)
    int cg  = t & 3;
    int row = t >> 2;               // 0..31
    int x = bx * 16 + cg * 4;
    int y = by * 32 + row;
    unsigned need = (1u << bx) | (1u << (16 + (y >> 4)));

    float px = (float)x - 127.5f;
    float py = (float)y - 127.5f;

    float a0 = 0.f, a1 = 0.f, a2 = 0.f, a3 = 0.f;

    #pragma unroll 2
    for (int i = 0; i < gN; i++) {
        float4 q1 = s1[i];
        unsigned mw = __float_as_uint(q1.z);
        if ((mw & need) != need) continue;   // warp-uniform skip
        float4 q0 = s0[i];
        float dx = px - q0.x;
        float dy = py - q0.y;
        float cA = q0.z;
        float h  = q1.x * dy;                // cC * dy
        float sB = q0.w * (dy * dy);         // cB * dy^2
        float o  = q1.y;

        float dxb = dx + 1.f;
        float dxc = dx + 2.f;
        float dxd = dx + 3.f;

        float w0 = ex2f(fmaf(dx,  fmaf(cA, dx,  h), sB));
        float w1 = ex2f(fmaf(dxb, fmaf(cA, dxb, h), sB));
        float w2 = ex2f(fmaf(dxc, fmaf(cA, dxc, h), sB));
        float w3 = ex2f(fmaf(dxd, fmaf(cA, dxd, h), sB));

        a0 = fmaf(w0, o, a0);
        a1 = fmaf(w1, o, a1);
        a2 = fmaf(w2, o, a2);
        a3 = fmaf(w3, o, a3);
    }

    int pix = y * RESI + x;
    *reinterpret_cast<float4*>(&d_partial[s * (RESI * RESI) + pix]) =
        make_float4(a0, a1, a2, a3);

    // ---- Phase 3: last-CTA-per-block reduction (deterministic order) ----
    __threadfence();                 // publish my partial gpu-wide
    __syncthreads();                 // all threads of this CTA fenced
    __shared__ unsigned s_old;
    if (t == 0) s_old = atomicAdd(&d_count[blk], 1u);
    __syncthreads();

    if (((s_old + 1) & (GSPLIT - 1)) == 0) {
        // Last of the GSPLIT CTAs for this pixel block: reduce in fixed order.
        const float4* p = reinterpret_cast<const float4*>(d_partial);
        int idx = pix >> 2;          // float4 index of my 4 pixels
        float4 a = __ldcg(&p[idx]);
        #pragma unroll
        for (int ss = 1; ss < GSPLIT; ss++) {
            float4 b = __ldcg(&p[ss * (RESI * RESI / 4) + idx]);
            a.x += b.x; a.y += b.y; a.z += b.z; a.w += b.w;
        }
        *reinterpret_cast<float4*>(&out[pix]) = a;
    }
}

// ---------------------------------------------------------------------------
extern "C" void kernel_launch(void* const* d_in, const int* in_sizes, int n_in,
                              void* d_out, int out_size) {
    const float* xyz      = (const float*)d_in[0];
    const float* scaling  = (const float*)d_in[1];
    const float* rotation = (const float*)d_in[2];
    const float* opacity  = (const float*)d_in[3];
    const float* rot      = (const float*)d_in[4];

    int N = in_sizes[0] / 3;
    if (N > MAXG) N = MAXG;

    splat_fused<<<NBLK * GSPLIT, 128>>>(xyz, scaling, rotation, opacity, rot,
                                        (float*)d_out, N);
}

// round 5
// speedup vs baseline: 1.1377x; 1.1367x over previous
#include <cuda_runtime.h>
#include <cstdint>

#define MAXG 1024
#define RESI 256
#define GSPLIT 16
#define GCHUNK 64    // MAXG / GSPLIT
#define NTILE 256    // 16x16 tiles

__device__ float    d_partial[GSPLIT * RESI * RESI];   // 4 MB scratch
__device__ unsigned d_count[NTILE];                    // zero-init; +GSPLIT per call per tile

__device__ __forceinline__ float ex2f(float x) {
    float y;
    asm("ex2.approx.ftz.f32 %0, %1;" : "=f"(y) : "f"(x));
    return y;
}

// ---------------------------------------------------------------------------
// One CTA = one 16x16 tile x one 64-gaussian chunk. 64 threads.
//   Phase 1: each thread preps ONE gaussian in registers, tests the
//            CTA-uniform tile mask, ballot+prefix -> dense compacted smem.
//   Phase 2: branch-free dense loop, 4 px per thread (one row each).
//   Phase 3: partial write; last CTA per tile reduces GSPLIT partials in
//            fixed order (deterministic) and writes out.
// ---------------------------------------------------------------------------
__global__ void __launch_bounds__(64) splat_fused(
        const float* __restrict__ xyz,
        const float* __restrict__ scaling,
        const float* __restrict__ rotation,
        const float* __restrict__ opacity,
        const float* __restrict__ rot,
        float* __restrict__ out,
        int N) {
    __shared__ float4 c0[GCHUNK];         // mx, my, cA, cB (compacted)
    __shared__ float2 c1[GCHUNK];         // cC, opacity    (compacted)
    __shared__ int    s_warpcnt[2];
    __shared__ unsigned s_old;

    const float RES = (float)RESI;
    int bid = blockIdx.x;
    int s   = bid & (GSPLIT - 1);   // gaussian split
    int blk = bid >> 4;             // tile 0..255
    int bx  = blk & 15;             // tile column
    int ty  = blk >> 4;             // tile row
    unsigned need = (1u << bx) | (1u << (16 + ty));

    int g0 = s * GCHUNK;
    int gN = N - g0;
    if (gN > GCHUNK) gN = GCHUNK;
    if (gN < 0) gN = 0;

    int t    = threadIdx.x;         // 0..63
    int lane = t & 31;
    int wid  = t >> 5;

    // ---- Phase 1: prep one gaussian in registers ----
    float mx = 0.f, my = 0.f, cA = 0.f, cB = 0.f, cC = 0.f, op = 0.f;
    bool pass = false;
    if (t < gN) {
        int i = g0 + t;
        float qr = rotation[4 * i + 0];
        float qx = rotation[4 * i + 1];
        float qy = rotation[4 * i + 2];
        float qz = rotation[4 * i + 3];
        float inv = rsqrtf(qr * qr + qx * qx + qy * qy + qz * qz);
        qr *= inv; qx *= inv; qy *= inv; qz *= inv;

        float R00 = 1.f - 2.f * (qy * qy + qz * qz);
        float R01 = 2.f * (qx * qy - qr * qz);
        float R02 = 2.f * (qx * qz + qr * qy);
        float R10 = 2.f * (qx * qy + qr * qz);
        float R11 = 1.f - 2.f * (qx * qx + qz * qz);
        float R12 = 2.f * (qy * qz - qr * qx);
        float R20 = 2.f * (qx * qz - qr * qy);
        float R21 = 2.f * (qy * qz + qr * qx);
        float R22 = 1.f - 2.f * (qx * qx + qy * qy);

        float sc0 = scaling[3 * i + 0];
        float sc1 = scaling[3 * i + 1];
        float sc2 = scaling[3 * i + 2];

        float L00 = R00 * sc0, L01 = R01 * sc1, L02 = R02 * sc2;
        float L10 = R10 * sc0, L11 = R11 * sc1, L12 = R12 * sc2;
        float L20 = R20 * sc0, L21 = R21 * sc1, L22 = R22 * sc2;

        float C00 = L00 * L00 + L01 * L01 + L02 * L02;
        float C01 = L00 * L10 + L01 * L11 + L02 * L12;
        float C02 = L00 * L20 + L01 * L21 + L02 * L22;
        float C11 = L10 * L10 + L11 * L11 + L12 * L12;
        float C12 = L10 * L20 + L11 * L21 + L12 * L22;
        float C22 = L20 * L20 + L21 * L21 + L22 * L22;

        float a00 = RES * rot[0], a01 = RES * rot[1], a02 = RES * rot[2];
        float a10 = RES * rot[3], a11 = RES * rot[4], a12 = RES * rot[5];

        float v0x = C00 * a00 + C01 * a01 + C02 * a02;
        float v0y = C01 * a00 + C11 * a01 + C12 * a02;
        float v0z = C02 * a00 + C12 * a01 + C22 * a02;
        float c00 = a00 * v0x + a01 * v0y + a02 * v0z;
        float c01 = a10 * v0x + a11 * v0y + a12 * v0z;
        float v1x = C00 * a10 + C01 * a11 + C02 * a12;
        float v1y = C01 * a10 + C11 * a11 + C12 * a12;
        float v1z = C02 * a10 + C12 * a11 + C22 * a12;
        float c11 = a10 * v1x + a11 * v1y + a12 * v1z;

        float det = c00 * c11 - c01 * c01;
        float mid = 0.5f * (c00 + c11);
        float sq = sqrtf(fmaxf(mid * mid - det, 0.1f));
        float lam = fmaxf(mid + sq, mid - sq);
        float radii = ceilf(3.0f * sqrtf(lam));

        mx = xyz[3 * i + 0] * (RES * 0.5f);
        my = xyz[3 * i + 1] * (RES * 0.5f);

        // mask test only for THIS tile (bx, ty)
        float rminx = fminf(fmaxf(mx - radii, 0.f), RES - 1.f);
        float rmaxx = fminf(fmaxf(mx + radii, 0.f), RES - 1.f);
        float rminy = fminf(fmaxf(my - radii, 0.f), RES - 1.f);
        float rmaxy = fminf(fmaxf(my + radii, 0.f), RES - 1.f);
        float tsx = (float)(bx * 16);
        float tsy = (float)(ty * 16);
        bool okx = fminf(rmaxx, tsx + 15.f) > fmaxf(rminx, tsx);
        bool oky = fminf(rmaxy, tsy + 15.f) > fmaxf(rminy, tsy);
        pass = okx && oky;

        float idet = 1.0f / det;
        const float L2E = 1.4426950408889634f;
        cA = -0.5f * L2E * (c11 * idet);
        cB = -0.5f * L2E * (c00 * idet);
        cC = -0.5f * L2E * (-2.0f * c01 * idet);
        op = opacity[i];
    }

    // compact (stable order: lane order within warp, warp0 before warp1)
    unsigned bal = __ballot_sync(0xffffffffu, pass);
    int within = __popc(bal & ((1u << lane) - 1u));
    if (lane == 0) s_warpcnt[wid] = __popc(bal);
    __syncthreads();
    int base = (wid == 1) ? s_warpcnt[0] : 0;
    int cnt = s_warpcnt[0] + s_warpcnt[1];
    if (pass) {
        int p = base + within;
        c0[p] = make_float4(mx, my, cA, cB);
        c1[p] = make_float2(cC, op);
    }
    __syncthreads();

    // ---- Phase 2: dense branch-free splat, 4 px per thread (one row) ----
    int cg  = t & 3;
    int row = t >> 2;               // 0..15
    int x = bx * 16 + cg * 4;
    int y = ty * 16 + row;

    float px = (float)x - 127.5f;
    float py = (float)y - 127.5f;

    float a0 = 0.f, a1 = 0.f, a2 = 0.f, a3 = 0.f;

    #pragma unroll 2
    for (int i = 0; i < cnt; i++) {
        float4 q0 = c0[i];
        float2 q1 = c1[i];
        float dx = px - q0.x;
        float dy = py - q0.y;
        float cAi = q0.z;
        float h  = q1.x * dy;               // cC * dy
        float sB = q0.w * (dy * dy);        // cB * dy^2
        float o  = q1.y;

        float dxb = dx + 1.f;
        float dxc = dx + 2.f;
        float dxd = dx + 3.f;

        float w0 = ex2f(fmaf(dx,  fmaf(cAi, dx,  h), sB));
        float w1 = ex2f(fmaf(dxb, fmaf(cAi, dxb, h), sB));
        float w2 = ex2f(fmaf(dxc, fmaf(cAi, dxc, h), sB));
        float w3 = ex2f(fmaf(dxd, fmaf(cAi, dxd, h), sB));

        a0 = fmaf(w0, o, a0);
        a1 = fmaf(w1, o, a1);
        a2 = fmaf(w2, o, a2);
        a3 = fmaf(w3, o, a3);
    }

    int pix = y * RESI + x;
    *reinterpret_cast<float4*>(&d_partial[s * (RESI * RESI) + pix]) =
        make_float4(a0, a1, a2, a3);

    // ---- Phase 3: last-CTA-per-tile reduction (deterministic order) ----
    __threadfence();
    __syncthreads();
    if (t == 0) s_old = atomicAdd(&d_count[blk], 1u);
    __syncthreads();

    if (((s_old + 1) & (GSPLIT - 1)) == 0) {
        const float4* p = reinterpret_cast<const float4*>(d_partial);
        int idx = pix >> 2;
        float4 a = __ldcg(&p[idx]);
        #pragma unroll
        for (int ss = 1; ss < GSPLIT; ss++) {
            float4 b = __ldcg(&p[ss * (RESI * RESI / 4) + idx]);
            a.x += b.x; a.y += b.y; a.z += b.z; a.w += b.w;
        }
        *reinterpret_cast<float4*>(&out[pix]) = a;
    }
}

// ---------------------------------------------------------------------------
extern "C" void kernel_launch(void* const* d_in, const int* in_sizes, int n_in,
                              void* d_out, int out_size) {
    const float* xyz      = (const float*)d_in[0];
    const float* scaling  = (const float*)d_in[1];
    const float* rotation = (const float*)d_in[2];
    const float* opacity  = (const float*)d_in[3];
    const float* rot      = (const float*)d_in[4];

    int N = in_sizes[0] / 3;
    if (N > MAXG) N = MAXG;

    splat_fused<<<NTILE * GSPLIT, 64>>>(xyz, scaling, rotation, opacity, rot,
                                        (float*)d_out, N);
}